// round 3
// baseline (speedup 1.0000x reference)
#include <cuda_runtime.h>
#include <cuda_bf16.h>
#include <stdint.h>

#define NUM_ROWS 16384
#define HDIM     2048
#define KSEL     4
#define NEXP     64
#define NTOT     (NUM_ROWS * KSEL)   /* 65536 expanded slots */
#define NCHUNK   256
#define CHUNK    (NTOT / NCHUNK)     /* 256 items per chunk */
#define NWARP    (CHUNK / 32)        /* 8 warps per chunk block */

/* output layout (floats) */
#define X_OFF   0
#define RI_OFF  ((size_t)NTOT * HDIM)                 /* 134217728 */
#define CNT_OFF (RI_OFF + NTOT)                        /* +65536 */
#define SC_OFF  (CNT_OFF + NEXP)                       /* +64 */

/* scratch (no cudaMalloc allowed) */
__device__ int g_chunkCounts[NCHUNK * NEXP];  /* pass1: counts; pass2: bases */
__device__ int g_dest[NTOT];
__device__ unsigned g_ticket  = 0;   /* monotonic across graph replays */
__device__ unsigned g_release = 0;   /* monotonic; one bump per launch  */

/* ---- K1: fused hist + scan + stable-dest (device-wide barrier) ----
 * 256 blocks x 256 threads: all co-resident on 148 SMs, so the spin
 * barrier cannot deadlock. Monotonic ticket/release counters make it
 * graph-replay safe with no reset needed.
 */
__global__ void __launch_bounds__(CHUNK) k_setup(const int* __restrict__ eidx,
                                                 const float* __restrict__ scale,
                                                 float* __restrict__ out) {
    __shared__ int sh[NEXP];
    __shared__ int shcnt[NWARP][NEXP];
    __shared__ int offs[NEXP];
    __shared__ unsigned s_launch;
    __shared__ int s_last;

    int t = threadIdx.x;
    int c = blockIdx.x;
    int w = t >> 5, lane = t & 31;

    /* ---- phase 1: per-chunk histogram ---- */
    if (t < NEXP) sh[t] = 0;
    __syncthreads();
    int i = c * CHUNK + t;
    int e = eidx[i];
    atomicAdd(&sh[e], 1);
    __syncthreads();
    if (t < NEXP) g_chunkCounts[c * NEXP + t] = sh[t];
    __threadfence();
    __syncthreads();

    /* ---- arrival ---- */
    if (t == 0) {
        unsigned ticket = atomicAdd(&g_ticket, 1u);
        s_launch = ticket / NCHUNK;
        s_last = ((ticket % NCHUNK) == NCHUNK - 1);
    }
    __syncthreads();

    if (s_last) {
        /* last-arriving block: all other histograms are globally visible */
        __threadfence();
        int tot = 0;
        if (t < NEXP) {
#pragma unroll 8
            for (int c2 = 0; c2 < NCHUNK; ++c2)
                tot += g_chunkCounts[c2 * NEXP + t];
            sh[t] = tot;
        }
        __syncthreads();
        if (t == 0) {
            int run = 0;
            for (int j = 0; j < NEXP; ++j) { offs[j] = run; run += sh[j]; }
        }
        __syncthreads();
        if (t < NEXP) {
            int run = offs[t];
#pragma unroll 8
            for (int c2 = 0; c2 < NCHUNK; ++c2) {
                int idx = c2 * NEXP + t;
                int v = g_chunkCounts[idx];
                g_chunkCounts[idx] = run;   /* counts -> stable bases */
                run += v;
            }
            out[CNT_OFF + t] = (float)tot;
        }
        __threadfence();
        __syncthreads();
        if (t == 0) atomicAdd(&g_release, 1u);
    } else {
        if (t == 0) {
            while (atomicAdd(&g_release, 0u) <= s_launch) { }
        }
        __syncthreads();
        __threadfence();
    }

    /* ---- phase 2: stable destination via match-based rank ---- */
    for (int j = t; j < NWARP * NEXP; j += CHUNK)
        ((int*)shcnt)[j] = 0;
    __syncthreads();

    unsigned m = __match_any_sync(0xffffffffu, e);
    int rank = __popc(m & ((1u << lane) - 1));
    if (rank == 0) shcnt[w][e] = __popc(m);
    __syncthreads();

    int off = 0;
#pragma unroll
    for (int w2 = 0; w2 < NWARP; ++w2)
        if (w2 < w) off += shcnt[w2][e];

    int d = g_chunkCounts[c * NEXP + e] + off + rank;
    g_dest[i] = d;
    out[RI_OFF + i] = (float)d;
    out[SC_OFF + d] = scale[i >> 2];
}

/* ---- K2: big gather copy: expanded_x[dest[i]] = x[i/K] ----
 * Streaming stores (evict-first) keep x resident in L2 (128MB vs 126MB L2),
 * cutting DRAM read traffic.
 */
__global__ void __launch_bounds__(128) k_copy(const float* __restrict__ x,
                                              float* __restrict__ out) {
    int i = blockIdx.x;          /* expanded slot 0..NTOT-1 */
    int src = i >> 2;            /* i / KSEL */
    int d = g_dest[i];
    const float4* __restrict__ s = (const float4*)(x + (size_t)src * HDIM);
    float4* __restrict__ o = (float4*)(out + X_OFF + (size_t)d * HDIM);
#pragma unroll
    for (int j = 0; j < 4; ++j) {
        int idx = threadIdx.x + j * 128;   /* 512 float4 per row */
        float4 v = s[idx];
        __stcs(o + idx, v);
    }
}

extern "C" void kernel_launch(void* const* d_in, const int* in_sizes, int n_in,
                              void* d_out, int out_size) {
    const float* x     = (const float*)d_in[0];
    const int*   eidx  = (const int*)d_in[1];
    const float* scale = (const float*)d_in[2];
    float* out = (float*)d_out;

    k_setup<<<NCHUNK, CHUNK>>>(eidx, scale, out);
    k_copy<<<NTOT, 128>>>(x, out);
}

// round 4
// speedup vs baseline: 1.0545x; 1.0545x over previous
#include <cuda_runtime.h>
#include <cuda_bf16.h>
#include <stdint.h>

#define NUM_ROWS 16384
#define HDIM     2048
#define KSEL     4
#define NEXP     64
#define NTOT     (NUM_ROWS * KSEL)   /* 65536 expanded slots */
#define NCHUNK   256
#define CHUNK    (NTOT / NCHUNK)     /* 256 items per chunk */
#define NWARP    (CHUNK / 32)        /* 8 warps per chunk block */

/* output layout (floats) */
#define X_OFF   0
#define RI_OFF  ((size_t)NTOT * HDIM)                 /* 134217728 */
#define CNT_OFF (RI_OFF + NTOT)                        /* +65536 */
#define SC_OFF  (CNT_OFF + NEXP)                       /* +64 */

/* scratch (no cudaMalloc allowed) */
__device__ int g_chunkCounts[NCHUNK * NEXP];  /* K1: counts; K2: stable bases */
__device__ int g_rank[NTOT];                  /* intra-chunk stable rank      */

/* ---- K1: per-chunk histogram + intra-chunk stable rank ---- */
__global__ void __launch_bounds__(CHUNK) k_rank(const int* __restrict__ eidx) {
    __shared__ int shcnt[NWARP][NEXP];
    int t = threadIdx.x;
    int c = blockIdx.x;
    int w = t >> 5, lane = t & 31;

    for (int j = t; j < NWARP * NEXP; j += CHUNK)
        ((int*)shcnt)[j] = 0;
    __syncthreads();

    int i = c * CHUNK + t;
    int e = eidx[i];
    unsigned m = __match_any_sync(0xffffffffu, e);
    int rank = __popc(m & ((1u << lane) - 1));
    if (rank == 0) shcnt[w][e] = __popc(m);
    __syncthreads();

    int off = 0;
#pragma unroll
    for (int w2 = 0; w2 < NWARP; ++w2)
        if (w2 < w) off += shcnt[w2][e];
    g_rank[i] = off + rank;

    if (t < NEXP) {
        int s = 0;
#pragma unroll
        for (int w2 = 0; w2 < NWARP; ++w2) s += shcnt[w2][t];
        g_chunkCounts[c * NEXP + t] = s;
    }
}

/* ---- K2: parallel scan -> stable per-chunk/per-expert bases + counts ----
 * 1024 threads = 64 experts x 16 groups; each group owns 16 chunks.
 */
__global__ void __launch_bounds__(1024) k_scan(float* __restrict__ out) {
    __shared__ int tot[NEXP];
    __shared__ int offs[NEXP];
    int t = threadIdx.x;
    int e = t >> 4;           /* expert 0..63 */
    int g = t & 15;           /* chunk-group 0..15 */

    int v[16];
    int partial = 0;
#pragma unroll
    for (int j = 0; j < 16; ++j) {
        v[j] = g_chunkCounts[(g * 16 + j) * NEXP + e];
        partial += v[j];
    }

    /* inclusive scan of partials across the 16-lane segment */
    int inc = partial;
#pragma unroll
    for (int d = 1; d < 16; d <<= 1) {
        int y = __shfl_up_sync(0xffffffffu, inc, d, 16);
        if (g >= d) inc += y;
    }
    int etotal = __shfl_sync(0xffffffffu, inc, 15, 16);
    if (g == 15) tot[e] = inc;
    __syncthreads();

    if (t == 0) {
        int run = 0;
        for (int j = 0; j < NEXP; ++j) { offs[j] = run; run += tot[j]; }
    }
    __syncthreads();
    if (t < NEXP) out[CNT_OFF + t] = (float)tot[t];

    int run = offs[e] + (inc - partial);   /* exclusive base for this group */
#pragma unroll
    for (int j = 0; j < 16; ++j) {
        g_chunkCounts[(g * 16 + j) * NEXP + e] = run;
        run += v[j];
    }
    (void)etotal;
}

/* ---- K3: big gather copy + final dest resolve + small outputs ---- */
__global__ void __launch_bounds__(128) k_copy(const float* __restrict__ x,
                                              const int* __restrict__ eidx,
                                              const float* __restrict__ scale,
                                              float* __restrict__ out) {
    int i = blockIdx.x;          /* expanded slot 0..NTOT-1 */
    int e = __ldg(eidx + i);
    int d = g_chunkCounts[(i >> 8) * NEXP + e] + g_rank[i];
    int src = i >> 2;

    const float4* __restrict__ s = (const float4*)(x + (size_t)src * HDIM);
    float4* __restrict__ o = (float4*)(out + X_OFF + (size_t)d * HDIM);
#pragma unroll
    for (int j = 0; j < 4; ++j) {
        int idx = threadIdx.x + j * 128;   /* 512 float4 per row */
        o[idx] = s[idx];
    }
    if (threadIdx.x == 0) {
        out[RI_OFF + i] = (float)d;
        out[SC_OFF + d] = scale[src];
    }
}

extern "C" void kernel_launch(void* const* d_in, const int* in_sizes, int n_in,
                              void* d_out, int out_size) {
    const float* x     = (const float*)d_in[0];
    const int*   eidx  = (const int*)d_in[1];
    const float* scale = (const float*)d_in[2];
    float* out = (float*)d_out;

    k_rank<<<NCHUNK, CHUNK>>>(eidx);
    k_scan<<<1, 1024>>>(out);
    k_copy<<<NTOT, 128>>>(x, eidx, scale, out);
}